// round 4
// baseline (speedup 1.0000x reference)
#include <cuda_runtime.h>
#include <cstdint>

#define BB 256
#define TT 1024
#define HH 128
#define II 19

// Scratch (device globals; no runtime allocation allowed)
__device__ float g_pre[BB * TT * HH];   // pre-activations for current layer
__device__ float g_out1[BB * TT * HH];  // layer-0 hidden outputs

typedef unsigned long long ull;

// packed f32x2 FMA: d = a*b + c elementwise on two packed fp32 lanes
__device__ __forceinline__ ull ffma2(ull a, ull b, ull c) {
    ull d;
    asm("fma.rn.f32x2 %0, %1, %2, %3;" : "=l"(d) : "l"(a), "l"(b), "l"(c));
    return d;
}

__device__ __forceinline__ ull fadd2(ull a, ull b) {
    ull d;
    asm("add.rn.f32x2 %0, %1, %2;" : "=l"(d) : "l"(a), "l"(b));
    return d;
}

__device__ __forceinline__ float hsum2(ull a) {
    float x, y;
    asm("mov.b64 {%0, %1}, %2;" : "=f"(x), "=f"(y) : "l"(a));
    return x + y;
}

// tanh(x) = 1 - 2/(exp(2x)+1), short critical path via approx MUFU ops.
// err ~1e-6 class; saturates correctly at +/-1.
__device__ __forceinline__ float fast_tanh(float x) {
    float e;
    asm("ex2.approx.f32 %0, %1;" : "=f"(e) : "f"(x * 2.8853900817779268f));
    float r;
    asm("rcp.approx.f32 %0, %1;" : "=f"(r) : "f"(e + 1.0f));
    return fmaf(-2.0f, r, 1.0f);
}

// ---------------------------------------------------------------------------
// proj0: pre = x @ W_ih0^T + (b_ih0 + b_hh0).  x:[B,T,19], W:[128,19]
// ---------------------------------------------------------------------------
#define ROWS0 8
__global__ void __launch_bounds__(128) proj0_kernel(
    const float* __restrict__ x,
    const float* __restrict__ Wih,
    const float* __restrict__ bih,
    const float* __restrict__ bhh)
{
    __shared__ float xs[ROWS0 * II];
    const int j   = threadIdx.x;
    const int blk = blockIdx.x;

    float w[II];
#pragma unroll
    for (int i = 0; i < II; i++) w[i] = Wih[j * II + i];
    const float bias = bih[j] + bhh[j];

    const float* src = x + (size_t)blk * ROWS0 * II;
    for (int i = j; i < ROWS0 * II; i += 128) xs[i] = src[i];
    __syncthreads();

#pragma unroll
    for (int r = 0; r < ROWS0; r++) {
        float acc = bias;
#pragma unroll
        for (int i = 0; i < II; i++) acc += xs[r * II + i] * w[i];
        g_pre[((size_t)blk * ROWS0 + r) * HH + j] = acc;
    }
}

// ---------------------------------------------------------------------------
// proj1: pre = out1 @ W_ih1^T + (b_ih1 + b_hh1).  out1:[B*T,128], W:[128,128]
// 128 threads (neuron j), ROWS1 rows per block, 4 rows at a time = 16
// independent FFMA2 chains. W row held in 64 packed f32x2 registers.
// ---------------------------------------------------------------------------
#define ROWS1 16
__global__ void __launch_bounds__(128, 2) proj1_kernel(
    const float* __restrict__ Wih,
    const float* __restrict__ bih,
    const float* __restrict__ bhh)
{
    __shared__ __align__(16) float in_s[ROWS1 * HH];
    const int j   = threadIdx.x;
    const int blk = blockIdx.x;

    ull w[64];
    {
        const ulonglong2* wr = (const ulonglong2*)(Wih + j * HH);
#pragma unroll
        for (int q = 0; q < 32; q++) {
            ulonglong2 t = wr[q];
            w[2 * q]     = t.x;
            w[2 * q + 1] = t.y;
        }
    }
    const float bias = bih[j] + bhh[j];

    {
        const float4* src = (const float4*)(g_out1 + (size_t)blk * ROWS1 * HH);
        float4*       dst = (float4*)in_s;
        for (int i = j; i < ROWS1 * HH / 4; i += 128) dst[i] = src[i];
    }
    __syncthreads();

#pragma unroll 1
    for (int r = 0; r < ROWS1; r += 4) {
        const ulonglong2* h0 = (const ulonglong2*)(in_s + (r + 0) * HH);
        const ulonglong2* h1 = (const ulonglong2*)(in_s + (r + 1) * HH);
        const ulonglong2* h2 = (const ulonglong2*)(in_s + (r + 2) * HH);
        const ulonglong2* h3 = (const ulonglong2*)(in_s + (r + 3) * HH);
        ull a0 = 0, a1 = 0, a2 = 0, a3 = 0;   // row r
        ull b0 = 0, b1 = 0, b2 = 0, b3 = 0;   // row r+1
        ull c0 = 0, c1 = 0, c2 = 0, c3 = 0;   // row r+2
        ull d0 = 0, d1 = 0, d2 = 0, d3 = 0;   // row r+3
#pragma unroll
        for (int q = 0; q < 16; q++) {
            ulonglong2 vA0 = h0[2 * q]; ulonglong2 vA1 = h0[2 * q + 1];
            ulonglong2 vB0 = h1[2 * q]; ulonglong2 vB1 = h1[2 * q + 1];
            ulonglong2 vC0 = h2[2 * q]; ulonglong2 vC1 = h2[2 * q + 1];
            ulonglong2 vD0 = h3[2 * q]; ulonglong2 vD1 = h3[2 * q + 1];
            a0 = ffma2(vA0.x, w[4 * q],     a0);
            b0 = ffma2(vB0.x, w[4 * q],     b0);
            c0 = ffma2(vC0.x, w[4 * q],     c0);
            d0 = ffma2(vD0.x, w[4 * q],     d0);
            a1 = ffma2(vA0.y, w[4 * q + 1], a1);
            b1 = ffma2(vB0.y, w[4 * q + 1], b1);
            c1 = ffma2(vC0.y, w[4 * q + 1], c1);
            d1 = ffma2(vD0.y, w[4 * q + 1], d1);
            a2 = ffma2(vA1.x, w[4 * q + 2], a2);
            b2 = ffma2(vB1.x, w[4 * q + 2], b2);
            c2 = ffma2(vC1.x, w[4 * q + 2], c2);
            d2 = ffma2(vD1.x, w[4 * q + 2], d2);
            a3 = ffma2(vA1.y, w[4 * q + 3], a3);
            b3 = ffma2(vB1.y, w[4 * q + 3], b3);
            c3 = ffma2(vC1.y, w[4 * q + 3], c3);
            d3 = ffma2(vD1.y, w[4 * q + 3], d3);
        }
        ull sa = fadd2(fadd2(a0, a1), fadd2(a2, a3));
        ull sb = fadd2(fadd2(b0, b1), fadd2(b2, b3));
        ull sc = fadd2(fadd2(c0, c1), fadd2(c2, c3));
        ull sd = fadd2(fadd2(d0, d1), fadd2(d2, d3));
        size_t base = ((size_t)blk * ROWS1 + r) * HH + j;
        g_pre[base]          = bias + hsum2(sa);
        g_pre[base + HH]     = bias + hsum2(sb);
        g_pre[base + 2 * HH] = bias + hsum2(sc);
        g_pre[base + 3 * HH] = bias + hsum2(sd);
    }
}

// ---------------------------------------------------------------------------
// scan: h_t = tanh(pre_t + W_hh h_{t-1}).  TWO batch rows PER THREAD:
// thread j of CTA b computes h[2b][j] and h[2b+1][j] every step, sharing one
// register-resident W_hh row. The two recurrence chains interleave as ILP
// inside one warp, so each row's serial tail (LDS->FMA->reduce->tanh->bar)
// is hidden behind the other's FMA stream. 128 CTAs x 128 threads, 1 CTA/SM,
// full 256-reg budget for load staging. One __syncthreads per step.
// outp == nullptr -> write g_out1 (layer 0), else write outp (layer 1).
// ---------------------------------------------------------------------------
__global__ void __launch_bounds__(128, 1) scan_kernel(
    const float* __restrict__ Whh,
    float* __restrict__ outp)
{
    __shared__ __align__(16) float hs[2][2][HH];  // [buf][row][j]
    const int j  = threadIdx.x;
    const int bA = blockIdx.x * 2;
    const int bB = bA + 1;

    ull w[64];
    {
        const ulonglong2* wr = (const ulonglong2*)(Whh + j * HH);
#pragma unroll
        for (int q = 0; q < 32; q++) {
            ulonglong2 t = wr[q];
            w[2 * q]     = t.x;
            w[2 * q + 1] = t.y;
        }
    }

    float* out = outp ? outp : g_out1;
    const float* prowA = g_pre + (size_t)bA * TT * HH + j;
    const float* prowB = g_pre + (size_t)bB * TT * HH + j;
    float*       orowA = out   + (size_t)bA * TT * HH + j;
    float*       orowB = out   + (size_t)bB * TT * HH + j;

    hs[0][0][j] = 0.0f;
    hs[0][1][j] = 0.0f;
    hs[1][0][j] = 0.0f;
    hs[1][1][j] = 0.0f;
    __syncthreads();

    // distance-2 prefetch of pre for both rows
    float pA0 = prowA[0];
    float pB0 = prowB[0];
    float pA1 = prowA[HH];
    float pB1 = prowB[HH];
    int cur = 0;

#pragma unroll 1
    for (int t = 0; t < TT; t++) {
        float pAn = (t + 2 < TT) ? prowA[(size_t)(t + 2) * HH] : 0.0f;
        float pBn = (t + 2 < TT) ? prowB[(size_t)(t + 2) * HH] : 0.0f;

        const ulonglong2* hA = (const ulonglong2*)hs[cur][0];
        const ulonglong2* hB = (const ulonglong2*)hs[cur][1];

        ull a0 = 0, a1 = 0, a2 = 0, a3 = 0, a4 = 0, a5 = 0, a6 = 0, a7 = 0;
        ull b0 = 0, b1 = 0, b2 = 0, b3 = 0, b4 = 0, b5 = 0, b6 = 0, b7 = 0;
#pragma unroll
        for (int q = 0; q < 8; q++) {
            ulonglong2 vA0 = hA[4 * q];
            ulonglong2 vA1 = hA[4 * q + 1];
            ulonglong2 vA2 = hA[4 * q + 2];
            ulonglong2 vA3 = hA[4 * q + 3];
            ulonglong2 vB0 = hB[4 * q];
            ulonglong2 vB1 = hB[4 * q + 1];
            ulonglong2 vB2 = hB[4 * q + 2];
            ulonglong2 vB3 = hB[4 * q + 3];
            a0 = ffma2(vA0.x, w[8 * q],     a0);
            b0 = ffma2(vB0.x, w[8 * q],     b0);
            a1 = ffma2(vA0.y, w[8 * q + 1], a1);
            b1 = ffma2(vB0.y, w[8 * q + 1], b1);
            a2 = ffma2(vA1.x, w[8 * q + 2], a2);
            b2 = ffma2(vB1.x, w[8 * q + 2], b2);
            a3 = ffma2(vA1.y, w[8 * q + 3], a3);
            b3 = ffma2(vB1.y, w[8 * q + 3], b3);
            a4 = ffma2(vA2.x, w[8 * q + 4], a4);
            b4 = ffma2(vB2.x, w[8 * q + 4], b4);
            a5 = ffma2(vA2.y, w[8 * q + 5], a5);
            b5 = ffma2(vB2.y, w[8 * q + 5], b5);
            a6 = ffma2(vA3.x, w[8 * q + 6], a6);
            b6 = ffma2(vB3.x, w[8 * q + 6], b6);
            a7 = ffma2(vA3.y, w[8 * q + 7], a7);
            b7 = ffma2(vB3.y, w[8 * q + 7], b7);
        }
        ull sA = fadd2(fadd2(fadd2(a0, a1), fadd2(a2, a3)),
                       fadd2(fadd2(a4, a5), fadd2(a6, a7)));
        ull sB = fadd2(fadd2(fadd2(b0, b1), fadd2(b2, b3)),
                       fadd2(fadd2(b4, b5), fadd2(b6, b7)));
        float hnA = fast_tanh(pA0 + hsum2(sA));
        float hnB = fast_tanh(pB0 + hsum2(sB));

        hs[cur ^ 1][0][j] = hnA;
        hs[cur ^ 1][1][j] = hnB;
        orowA[(size_t)t * HH] = hnA;
        orowB[(size_t)t * HH] = hnB;
        __syncthreads();

        pA0 = pA1; pA1 = pAn;
        pB0 = pB1; pB1 = pBn;
        cur ^= 1;
    }
}

// ---------------------------------------------------------------------------
extern "C" void kernel_launch(void* const* d_in, const int* in_sizes, int n_in,
                              void* d_out, int out_size)
{
    const float* x     = (const float*)d_in[0];
    const float* Wih0  = (const float*)d_in[1];
    const float* Whh0  = (const float*)d_in[2];
    const float* bih0  = (const float*)d_in[3];
    const float* bhh0  = (const float*)d_in[4];
    const float* Wih1  = (const float*)d_in[5];
    const float* Whh1  = (const float*)d_in[6];
    const float* bih1  = (const float*)d_in[7];
    const float* bhh1  = (const float*)d_in[8];
    float* out = (float*)d_out;

    // layer 0
    proj0_kernel<<<BB * TT / ROWS0, 128>>>(x, Wih0, bih0, bhh0);
    scan_kernel<<<BB / 2, 128>>>(Whh0, nullptr);

    // layer 1
    proj1_kernel<<<BB * TT / ROWS1, 128>>>(Wih1, bih1, bhh1);
    scan_kernel<<<BB / 2, 128>>>(Whh1, out);
}

// round 5
// speedup vs baseline: 1.3607x; 1.3607x over previous
#include <cuda_runtime.h>
#include <cstdint>

#define BB 256
#define TT 1024
#define HH 128
#define II 19
#define STG_T 16   // timesteps per cp.async stage

// Scratch (device globals; no runtime allocation allowed)
__device__ float g_pre[BB * TT * HH];   // pre-activations for current layer
__device__ float g_out1[BB * TT * HH];  // layer-0 hidden outputs

typedef unsigned long long ull;

// packed f32x2 FMA: d = a*b + c elementwise on two packed fp32 lanes
__device__ __forceinline__ ull ffma2(ull a, ull b, ull c) {
    ull d;
    asm("fma.rn.f32x2 %0, %1, %2, %3;" : "=l"(d) : "l"(a), "l"(b), "l"(c));
    return d;
}

__device__ __forceinline__ ull fadd2(ull a, ull b) {
    ull d;
    asm("add.rn.f32x2 %0, %1, %2;" : "=l"(d) : "l"(a), "l"(b));
    return d;
}

__device__ __forceinline__ float hsum2(ull a) {
    float x, y;
    asm("mov.b64 {%0, %1}, %2;" : "=f"(x), "=f"(y) : "l"(a));
    return x + y;
}

// tanh(x) = 1 - 2/(exp(2x)+1) via approx MUFU; ~1e-6 err, saturates to +/-1
__device__ __forceinline__ float fast_tanh(float x) {
    float e;
    asm("ex2.approx.f32 %0, %1;" : "=f"(e) : "f"(x * 2.8853900817779268f));
    float r;
    asm("rcp.approx.f32 %0, %1;" : "=f"(r) : "f"(e + 1.0f));
    return fmaf(-2.0f, r, 1.0f);
}

__device__ __forceinline__ uint32_t s2u(const void* p) {
    return (uint32_t)__cvta_generic_to_shared(p);
}
#define CP_ASYNC16(dst, src) \
    asm volatile("cp.async.ca.shared.global [%0], [%1], 16;" :: "r"(dst), "l"(src))
#define CP_COMMIT() asm volatile("cp.async.commit_group;" ::: "memory")
#define CP_WAIT0()  asm volatile("cp.async.wait_group 0;" ::: "memory")
#define CP_WAIT1()  asm volatile("cp.async.wait_group 1;" ::: "memory")

// ---------------------------------------------------------------------------
// proj0: pre = x @ W_ih0^T + (b_ih0 + b_hh0).  x:[B,T,19], W:[128,19]
// ---------------------------------------------------------------------------
#define ROWS0 8
__global__ void __launch_bounds__(128) proj0_kernel(
    const float* __restrict__ x,
    const float* __restrict__ Wih,
    const float* __restrict__ bih,
    const float* __restrict__ bhh)
{
    __shared__ float xs[ROWS0 * II];
    const int j   = threadIdx.x;
    const int blk = blockIdx.x;

    float w[II];
#pragma unroll
    for (int i = 0; i < II; i++) w[i] = Wih[j * II + i];
    const float bias = bih[j] + bhh[j];

    const float* src = x + (size_t)blk * ROWS0 * II;
    for (int i = j; i < ROWS0 * II; i += 128) xs[i] = src[i];
    __syncthreads();

#pragma unroll
    for (int r = 0; r < ROWS0; r++) {
        float acc = bias;
#pragma unroll
        for (int i = 0; i < II; i++) acc += xs[r * II + i] * w[i];
        g_pre[((size_t)blk * ROWS0 + r) * HH + j] = acc;
    }
}

// ---------------------------------------------------------------------------
// proj1: pre = out1 @ W_ih1^T + (b_ih1 + b_hh1).  out1:[B*T,128], W:[128,128]
// Input tile staged via cp.async overlapped with the W LDGs.
// ---------------------------------------------------------------------------
#define ROWS1 16
__global__ void __launch_bounds__(128, 2) proj1_kernel(
    const float* __restrict__ Wih,
    const float* __restrict__ bih,
    const float* __restrict__ bhh)
{
    __shared__ __align__(16) float in_s[ROWS1 * HH];
    const int j   = threadIdx.x;
    const int blk = blockIdx.x;

    // kick off async input-tile copy (8 KB = 512 x 16B chunks)
    {
        uint32_t dbase = s2u(in_s);
        const float* src = g_out1 + (size_t)blk * ROWS1 * HH;
#pragma unroll
        for (int it = 0; it < 4; it++) {
            int lin = it * 128 + j;
            CP_ASYNC16(dbase + lin * 16, src + lin * 4);
        }
        CP_COMMIT();
    }

    // W_ih1 row j as 64 packed pairs (overlaps with cp.async flight)
    ull w[64];
    {
        const ulonglong2* wr = (const ulonglong2*)(Wih + j * HH);
#pragma unroll
        for (int q = 0; q < 32; q++) {
            ulonglong2 t = wr[q];
            w[2 * q]     = t.x;
            w[2 * q + 1] = t.y;
        }
    }
    const float bias = bih[j] + bhh[j];

    CP_WAIT0();
    __syncthreads();

#pragma unroll 1
    for (int r = 0; r < ROWS1; r += 4) {
        const ulonglong2* h0 = (const ulonglong2*)(in_s + (r + 0) * HH);
        const ulonglong2* h1 = (const ulonglong2*)(in_s + (r + 1) * HH);
        const ulonglong2* h2 = (const ulonglong2*)(in_s + (r + 2) * HH);
        const ulonglong2* h3 = (const ulonglong2*)(in_s + (r + 3) * HH);
        ull a0 = 0, a1 = 0, a2 = 0, a3 = 0;
        ull b0 = 0, b1 = 0, b2 = 0, b3 = 0;
        ull c0 = 0, c1 = 0, c2 = 0, c3 = 0;
        ull d0 = 0, d1 = 0, d2 = 0, d3 = 0;
#pragma unroll
        for (int q = 0; q < 16; q++) {
            ulonglong2 vA0 = h0[2 * q]; ulonglong2 vA1 = h0[2 * q + 1];
            ulonglong2 vB0 = h1[2 * q]; ulonglong2 vB1 = h1[2 * q + 1];
            ulonglong2 vC0 = h2[2 * q]; ulonglong2 vC1 = h2[2 * q + 1];
            ulonglong2 vD0 = h3[2 * q]; ulonglong2 vD1 = h3[2 * q + 1];
            a0 = ffma2(vA0.x, w[4 * q],     a0);
            b0 = ffma2(vB0.x, w[4 * q],     b0);
            c0 = ffma2(vC0.x, w[4 * q],     c0);
            d0 = ffma2(vD0.x, w[4 * q],     d0);
            a1 = ffma2(vA0.y, w[4 * q + 1], a1);
            b1 = ffma2(vB0.y, w[4 * q + 1], b1);
            c1 = ffma2(vC0.y, w[4 * q + 1], c1);
            d1 = ffma2(vD0.y, w[4 * q + 1], d1);
            a2 = ffma2(vA1.x, w[4 * q + 2], a2);
            b2 = ffma2(vB1.x, w[4 * q + 2], b2);
            c2 = ffma2(vC1.x, w[4 * q + 2], c2);
            d2 = ffma2(vD1.x, w[4 * q + 2], d2);
            a3 = ffma2(vA1.y, w[4 * q + 3], a3);
            b3 = ffma2(vB1.y, w[4 * q + 3], b3);
            c3 = ffma2(vC1.y, w[4 * q + 3], c3);
            d3 = ffma2(vD1.y, w[4 * q + 3], d3);
        }
        ull sa = fadd2(fadd2(a0, a1), fadd2(a2, a3));
        ull sb = fadd2(fadd2(b0, b1), fadd2(b2, b3));
        ull sc = fadd2(fadd2(c0, c1), fadd2(c2, c3));
        ull sd = fadd2(fadd2(d0, d1), fadd2(d2, d3));
        size_t base = ((size_t)blk * ROWS1 + r) * HH + j;
        g_pre[base]          = bias + hsum2(sa);
        g_pre[base + HH]     = bias + hsum2(sb);
        g_pre[base + 2 * HH] = bias + hsum2(sc);
        g_pre[base + 3 * HH] = bias + hsum2(sd);
    }
}

// ---------------------------------------------------------------------------
// scan: h_t = tanh(pre_t + W_hh h_{t-1}). Two batch rows per thread (shared
// register-resident W_hh row, 16 independent FFMA2 chains). pre is staged
// into shared by cp.async in 16-step double-buffered stages, issued one full
// stage (~5K cyc) ahead -> DRAM latency fully hidden; inner loop reads p via
// conflict-free LDS. 128 CTAs x 128 threads.
// outp == nullptr -> write g_out1 (layer 0), else write outp (layer 1).
// ---------------------------------------------------------------------------
struct DualAcc { float hA, hB; };

__device__ __forceinline__ DualAcc scan_step(
    const float* hAp, const float* hBp, const ull* w, float pA, float pB)
{
    const ulonglong2* hA = (const ulonglong2*)hAp;
    const ulonglong2* hB = (const ulonglong2*)hBp;
    ull a0 = 0, a1 = 0, a2 = 0, a3 = 0, a4 = 0, a5 = 0, a6 = 0, a7 = 0;
    ull b0 = 0, b1 = 0, b2 = 0, b3 = 0, b4 = 0, b5 = 0, b6 = 0, b7 = 0;
#pragma unroll
    for (int q = 0; q < 8; q++) {
        ulonglong2 vA0 = hA[4 * q];
        ulonglong2 vA1 = hA[4 * q + 1];
        ulonglong2 vA2 = hA[4 * q + 2];
        ulonglong2 vA3 = hA[4 * q + 3];
        ulonglong2 vB0 = hB[4 * q];
        ulonglong2 vB1 = hB[4 * q + 1];
        ulonglong2 vB2 = hB[4 * q + 2];
        ulonglong2 vB3 = hB[4 * q + 3];
        a0 = ffma2(vA0.x, w[8 * q],     a0);
        b0 = ffma2(vB0.x, w[8 * q],     b0);
        a1 = ffma2(vA0.y, w[8 * q + 1], a1);
        b1 = ffma2(vB0.y, w[8 * q + 1], b1);
        a2 = ffma2(vA1.x, w[8 * q + 2], a2);
        b2 = ffma2(vB1.x, w[8 * q + 2], b2);
        a3 = ffma2(vA1.y, w[8 * q + 3], a3);
        b3 = ffma2(vB1.y, w[8 * q + 3], b3);
        a4 = ffma2(vA2.x, w[8 * q + 4], a4);
        b4 = ffma2(vB2.x, w[8 * q + 4], b4);
        a5 = ffma2(vA2.y, w[8 * q + 5], a5);
        b5 = ffma2(vB2.y, w[8 * q + 5], b5);
        a6 = ffma2(vA3.x, w[8 * q + 6], a6);
        b6 = ffma2(vB3.x, w[8 * q + 6], b6);
        a7 = ffma2(vA3.y, w[8 * q + 7], a7);
        b7 = ffma2(vB3.y, w[8 * q + 7], b7);
    }
    ull sA = fadd2(fadd2(fadd2(a0, a1), fadd2(a2, a3)),
                   fadd2(fadd2(a4, a5), fadd2(a6, a7)));
    ull sB = fadd2(fadd2(fadd2(b0, b1), fadd2(b2, b3)),
                   fadd2(fadd2(b4, b5), fadd2(b6, b7)));
    DualAcc r;
    r.hA = fast_tanh(pA + hsum2(sA));
    r.hB = fast_tanh(pB + hsum2(sB));
    return r;
}

__global__ void __launch_bounds__(128, 1) scan_kernel(
    const float* __restrict__ Whh,
    float* __restrict__ outp)
{
    __shared__ __align__(16) float hs[2][2][HH];          // [buf][row][j]
    __shared__ __align__(16) float ps[2][STG_T * 2 * HH]; // [buf][(t*2+row)*HH + j]
    const int j  = threadIdx.x;
    const int bA = blockIdx.x * 2;
    const int bB = bA + 1;

    const float* preA = g_pre + (size_t)bA * TT * HH;
    const float* preB = g_pre + (size_t)bB * TT * HH;

    // kick off stage 0 and stage 1 refills before the (long-latency) W load
    {
#pragma unroll
        for (int s = 0; s < 2; s++) {
            uint32_t dbase = s2u(ps[s]);
            int t0 = s * STG_T;
#pragma unroll
            for (int it = 0; it < 8; it++) {
                int lin = it * 128 + j;          // [0,1024) 16B chunks
                int c   = lin & 31;              // chunk within (t,row)
                int pr  = lin >> 5;              // (t,row) pair index
                int t   = pr >> 1;
                int row = pr & 1;
                const float* src = (row ? preB : preA) + (size_t)(t0 + t) * HH + c * 4;
                CP_ASYNC16(dbase + (((t * 2 + row) * HH) + c * 4) * 4, src);
            }
            CP_COMMIT();
        }
    }

    // W_hh row j as 64 packed pairs
    ull w[64];
    {
        const ulonglong2* wr = (const ulonglong2*)(Whh + j * HH);
#pragma unroll
        for (int q = 0; q < 32; q++) {
            ulonglong2 t = wr[q];
            w[2 * q]     = t.x;
            w[2 * q + 1] = t.y;
        }
    }

    float* out = outp ? outp : g_out1;
    float* orowA = out + (size_t)bA * TT * HH + j;
    float* orowB = out + (size_t)bB * TT * HH + j;

    hs[0][0][j] = 0.0f;
    hs[0][1][j] = 0.0f;
    __syncthreads();

    const int nst = TT / STG_T;
#pragma unroll 1
    for (int s = 0; s < nst; s++) {
        const int buf = s & 1;
        // stage s's copy must be complete; allow the one newer group in flight
        if (s + 1 < nst) { CP_WAIT1(); } else { CP_WAIT0(); }
        __syncthreads();

        const float* pst = ps[buf];
        const int tbase = s * STG_T;
#pragma unroll 1
        for (int tl = 0; tl < STG_T; tl += 2) {
            // even step: hs[0] -> hs[1]
            {
                float pA = pst[(tl * 2 + 0) * HH + j];
                float pB = pst[(tl * 2 + 1) * HH + j];
                DualAcc rr = scan_step(hs[0][0], hs[0][1], w, pA, pB);
                hs[1][0][j] = rr.hA;
                hs[1][1][j] = rr.hB;
                size_t off = (size_t)(tbase + tl) * HH;
                orowA[off] = rr.hA;
                orowB[off] = rr.hB;
                __syncthreads();
            }
            // odd step: hs[1] -> hs[0]
            {
                float pA = pst[((tl + 1) * 2 + 0) * HH + j];
                float pB = pst[((tl + 1) * 2 + 1) * HH + j];
                DualAcc rr = scan_step(hs[1][0], hs[1][1], w, pA, pB);
                hs[0][0][j] = rr.hA;
                hs[0][1][j] = rr.hB;
                size_t off = (size_t)(tbase + tl + 1) * HH;
                orowA[off] = rr.hA;
                orowB[off] = rr.hB;
                __syncthreads();
            }
        }

        // refill stage s+2 into this (now fully consumed) buffer
        if (s + 2 < nst) {
            uint32_t dbase = s2u(ps[buf]);
            int t0 = (s + 2) * STG_T;
#pragma unroll
            for (int it = 0; it < 8; it++) {
                int lin = it * 128 + j;
                int c   = lin & 31;
                int pr  = lin >> 5;
                int t   = pr >> 1;
                int row = pr & 1;
                const float* src = (row ? preB : preA) + (size_t)(t0 + t) * HH + c * 4;
                CP_ASYNC16(dbase + (((t * 2 + row) * HH) + c * 4) * 4, src);
            }
            CP_COMMIT();
        }
    }
}

// ---------------------------------------------------------------------------
extern "C" void kernel_launch(void* const* d_in, const int* in_sizes, int n_in,
                              void* d_out, int out_size)
{
    const float* x     = (const float*)d_in[0];
    const float* Wih0  = (const float*)d_in[1];
    const float* Whh0  = (const float*)d_in[2];
    const float* bih0  = (const float*)d_in[3];
    const float* bhh0  = (const float*)d_in[4];
    const float* Wih1  = (const float*)d_in[5];
    const float* Whh1  = (const float*)d_in[6];
    const float* bih1  = (const float*)d_in[7];
    const float* bhh1  = (const float*)d_in[8];
    float* out = (float*)d_out;

    // layer 0
    proj0_kernel<<<BB * TT / ROWS0, 128>>>(x, Wih0, bih0, bhh0);
    scan_kernel<<<BB / 2, 128>>>(Whh0, nullptr);

    // layer 1
    proj1_kernel<<<BB * TT / ROWS1, 128>>>(Wih1, bih1, bhh1);
    scan_kernel<<<BB / 2, 128>>>(Whh1, out);
}

// round 6
// speedup vs baseline: 1.7374x; 1.2768x over previous
#include <cuda_runtime.h>
#include <cstdint>

#define BB 256
#define TT 1024
#define HH 128
#define II 19
#define STG_T 16   // timesteps per cp.async stage in scan

// Scratch (device globals; no runtime allocation allowed)
__device__ float g_pre[BB * TT * HH];   // pre-activations for current layer
__device__ float g_out1[BB * TT * HH];  // layer-0 hidden outputs

typedef unsigned long long ull;

__device__ __forceinline__ ull ffma2(ull a, ull b, ull c) {
    ull d;
    asm("fma.rn.f32x2 %0, %1, %2, %3;" : "=l"(d) : "l"(a), "l"(b), "l"(c));
    return d;
}

__device__ __forceinline__ ull fadd2(ull a, ull b) {
    ull d;
    asm("add.rn.f32x2 %0, %1, %2;" : "=l"(d) : "l"(a), "l"(b));
    return d;
}

__device__ __forceinline__ float hsum2(ull a) {
    float x, y;
    asm("mov.b64 {%0, %1}, %2;" : "=f"(x), "=f"(y) : "l"(a));
    return x + y;
}

// tanh(x) = 1 - 2/(exp(2x)+1) via approx MUFU; ~1e-6 err, saturates to +/-1
__device__ __forceinline__ float fast_tanh(float x) {
    float e;
    asm("ex2.approx.f32 %0, %1;" : "=f"(e) : "f"(x * 2.8853900817779268f));
    float r;
    asm("rcp.approx.f32 %0, %1;" : "=f"(r) : "f"(e + 1.0f));
    return fmaf(-2.0f, r, 1.0f);
}

__device__ __forceinline__ uint32_t s2u(const void* p) {
    return (uint32_t)__cvta_generic_to_shared(p);
}
#define CP_ASYNC16(dst, src) \
    asm volatile("cp.async.ca.shared.global [%0], [%1], 16;" :: "r"(dst), "l"(src))
#define CP_COMMIT() asm volatile("cp.async.commit_group;" ::: "memory")
#define CP_WAIT0()  asm volatile("cp.async.wait_group 0;" ::: "memory")
#define CP_WAIT1()  asm volatile("cp.async.wait_group 1;" ::: "memory")

// ---------------------------------------------------------------------------
// proj0: pre = x @ W_ih0^T + (b_ih0 + b_hh0).  x:[B,T,19], W:[128,19]
// ---------------------------------------------------------------------------
#define ROWS0 8
__global__ void __launch_bounds__(128) proj0_kernel(
    const float* __restrict__ x,
    const float* __restrict__ Wih,
    const float* __restrict__ bih,
    const float* __restrict__ bhh)
{
    __shared__ float xs[ROWS0 * II];
    const int j   = threadIdx.x;
    const int blk = blockIdx.x;

    float w[II];
#pragma unroll
    for (int i = 0; i < II; i++) w[i] = Wih[j * II + i];
    const float bias = bih[j] + bhh[j];

    const float* src = x + (size_t)blk * ROWS0 * II;
    for (int i = j; i < ROWS0 * II; i += 128) xs[i] = src[i];
    __syncthreads();

#pragma unroll
    for (int r = 0; r < ROWS0; r++) {
        float acc = bias;
#pragma unroll
        for (int i = 0; i < II; i++) acc += xs[r * II + i] * w[i];
        g_pre[((size_t)blk * ROWS0 + r) * HH + j] = acc;
    }
}

// ---------------------------------------------------------------------------
// proj1 (persistent): pre = out1 @ W_ih1^T + bias.  out1:[B*T,128], W:[128,128]
// 296 CTAs; W row per thread loaded ONCE into 64 packed regs; input tiles
// double-buffered via cp.async, copy of tile k+1 overlaps compute of tile k.
// ---------------------------------------------------------------------------
#define ROWS1 16
#define NT1   (BB * TT / ROWS1)
#define PJ1_GRID 296

__device__ __forceinline__ void pj1_prefetch(float* dst, int tile, int j) {
    uint32_t dbase = s2u(dst);
    const float* src = g_out1 + (size_t)tile * ROWS1 * HH;
#pragma unroll
    for (int it = 0; it < 4; it++) {
        int lin = it * 128 + j;                 // [0,512) 16B chunks
        CP_ASYNC16(dbase + lin * 16, src + lin * 4);
    }
}

__global__ void __launch_bounds__(128, 2) proj1_kernel(
    const float* __restrict__ Wih,
    const float* __restrict__ bih,
    const float* __restrict__ bhh)
{
    __shared__ __align__(16) float in_s[2][ROWS1 * HH];
    const int j = threadIdx.x;

    int t = blockIdx.x;
    if (t < NT1) pj1_prefetch(in_s[0], t, j);
    CP_COMMIT();

    // W_ih1 row j as 64 packed pairs (overlaps with cp.async flight)
    ull w[64];
    {
        const ulonglong2* wr = (const ulonglong2*)(Wih + j * HH);
#pragma unroll
        for (int q = 0; q < 32; q++) {
            ulonglong2 tt = wr[q];
            w[2 * q]     = tt.x;
            w[2 * q + 1] = tt.y;
        }
    }
    const float bias = bih[j] + bhh[j];

    int buf = 0;
#pragma unroll 1
    while (t < NT1) {
        const int tn = t + PJ1_GRID;
        CP_WAIT0();
        __syncthreads();
        if (tn < NT1) { pj1_prefetch(in_s[buf ^ 1], tn, j); }
        CP_COMMIT();

        const float* ins = in_s[buf];
#pragma unroll 1
        for (int r = 0; r < ROWS1; r += 4) {
            const ulonglong2* h0 = (const ulonglong2*)(ins + (r + 0) * HH);
            const ulonglong2* h1 = (const ulonglong2*)(ins + (r + 1) * HH);
            const ulonglong2* h2 = (const ulonglong2*)(ins + (r + 2) * HH);
            const ulonglong2* h3 = (const ulonglong2*)(ins + (r + 3) * HH);
            ull a0 = 0, a1 = 0, a2 = 0, a3 = 0;
            ull b0 = 0, b1 = 0, b2 = 0, b3 = 0;
            ull c0 = 0, c1 = 0, c2 = 0, c3 = 0;
            ull d0 = 0, d1 = 0, d2 = 0, d3 = 0;
#pragma unroll
            for (int q = 0; q < 16; q++) {
                ulonglong2 vA0 = h0[2 * q]; ulonglong2 vA1 = h0[2 * q + 1];
                ulonglong2 vB0 = h1[2 * q]; ulonglong2 vB1 = h1[2 * q + 1];
                ulonglong2 vC0 = h2[2 * q]; ulonglong2 vC1 = h2[2 * q + 1];
                ulonglong2 vD0 = h3[2 * q]; ulonglong2 vD1 = h3[2 * q + 1];
                a0 = ffma2(vA0.x, w[4 * q],     a0);
                b0 = ffma2(vB0.x, w[4 * q],     b0);
                c0 = ffma2(vC0.x, w[4 * q],     c0);
                d0 = ffma2(vD0.x, w[4 * q],     d0);
                a1 = ffma2(vA0.y, w[4 * q + 1], a1);
                b1 = ffma2(vB0.y, w[4 * q + 1], b1);
                c1 = ffma2(vC0.y, w[4 * q + 1], c1);
                d1 = ffma2(vD0.y, w[4 * q + 1], d1);
                a2 = ffma2(vA1.x, w[4 * q + 2], a2);
                b2 = ffma2(vB1.x, w[4 * q + 2], b2);
                c2 = ffma2(vC1.x, w[4 * q + 2], c2);
                d2 = ffma2(vD1.x, w[4 * q + 2], d2);
                a3 = ffma2(vA1.y, w[4 * q + 3], a3);
                b3 = ffma2(vB1.y, w[4 * q + 3], b3);
                c3 = ffma2(vC1.y, w[4 * q + 3], c3);
                d3 = ffma2(vD1.y, w[4 * q + 3], d3);
            }
            ull sa = fadd2(fadd2(a0, a1), fadd2(a2, a3));
            ull sb = fadd2(fadd2(b0, b1), fadd2(b2, b3));
            ull sc = fadd2(fadd2(c0, c1), fadd2(c2, c3));
            ull sd = fadd2(fadd2(d0, d1), fadd2(d2, d3));
            size_t base = ((size_t)t * ROWS1 + r) * HH + j;
            g_pre[base]          = bias + hsum2(sa);
            g_pre[base + HH]     = bias + hsum2(sb);
            g_pre[base + 2 * HH] = bias + hsum2(sc);
            g_pre[base + 3 * HH] = bias + hsum2(sd);
        }
        t = tn;
        buf ^= 1;
    }
}

// ---------------------------------------------------------------------------
// scan: h_t = tanh(pre_t + W_hh h_{t-1}).  ONE batch row per CTA, 256 CTAs,
// 2 CTAs/SM: two independent recurrences per SMSP, each warp's serial tail
// (reduce->tanh->STS->bar) hides under the other CTA's FFMA2 stream.
// W_hh row j register-resident; pre staged by cp.async in 16-step
// double-buffered stages (DRAM latency hidden by a full stage of slack).
// outp == nullptr -> write g_out1 (layer 0), else write outp (layer 1).
// ---------------------------------------------------------------------------
__device__ __forceinline__ void scan_prefetch(float* dst, const float* pre,
                                              int t0, int j) {
    uint32_t dbase = s2u(dst);
#pragma unroll
    for (int it = 0; it < 4; it++) {
        int lin = it * 128 + j;                 // [0,512) 16B chunks
        int tt  = lin >> 5;                     // timestep within stage
        int c   = lin & 31;                     // 16B chunk within row
        CP_ASYNC16(dbase + lin * 16, pre + (size_t)(t0 + tt) * HH + c * 4);
    }
}

__device__ __forceinline__ float scan_step1(const float* hp, const ull* w, float p) {
    const ulonglong2* h2 = (const ulonglong2*)hp;
    ull a0 = 0, a1 = 0, a2 = 0, a3 = 0, a4 = 0, a5 = 0, a6 = 0, a7 = 0;
#pragma unroll
    for (int q = 0; q < 8; q++) {
        ulonglong2 v0 = h2[4 * q];
        ulonglong2 v1 = h2[4 * q + 1];
        ulonglong2 v2 = h2[4 * q + 2];
        ulonglong2 v3 = h2[4 * q + 3];
        a0 = ffma2(v0.x, w[8 * q],     a0);
        a1 = ffma2(v0.y, w[8 * q + 1], a1);
        a2 = ffma2(v1.x, w[8 * q + 2], a2);
        a3 = ffma2(v1.y, w[8 * q + 3], a3);
        a4 = ffma2(v2.x, w[8 * q + 4], a4);
        a5 = ffma2(v2.y, w[8 * q + 5], a5);
        a6 = ffma2(v3.x, w[8 * q + 6], a6);
        a7 = ffma2(v3.y, w[8 * q + 7], a7);
    }
    ull s = fadd2(fadd2(fadd2(a0, a1), fadd2(a2, a3)),
                  fadd2(fadd2(a4, a5), fadd2(a6, a7)));
    return fast_tanh(p + hsum2(s));
}

__global__ void __launch_bounds__(128, 2) scan_kernel(
    const float* __restrict__ Whh,
    float* __restrict__ outp)
{
    __shared__ __align__(16) float hs[2][HH];            // double-buffered h
    __shared__ __align__(16) float ps[2][STG_T * HH];    // staged pre
    const int j = threadIdx.x;
    const int b = blockIdx.x;

    const float* pre = g_pre + (size_t)b * TT * HH;

    // stages 0 and 1 in flight before the long-latency W load
    scan_prefetch(ps[0], pre, 0, j);
    CP_COMMIT();
    scan_prefetch(ps[1], pre, STG_T, j);
    CP_COMMIT();

    ull w[64];
    {
        const ulonglong2* wr = (const ulonglong2*)(Whh + j * HH);
#pragma unroll
        for (int q = 0; q < 32; q++) {
            ulonglong2 t = wr[q];
            w[2 * q]     = t.x;
            w[2 * q + 1] = t.y;
        }
    }

    float* out  = outp ? outp : g_out1;
    float* orow = out + (size_t)b * TT * HH + j;

    hs[0][j] = 0.0f;
    __syncthreads();

    const int nst = TT / STG_T;
#pragma unroll 1
    for (int s = 0; s < nst; s++) {
        const int buf = s & 1;
        if (s + 1 < nst) { CP_WAIT1(); } else { CP_WAIT0(); }
        __syncthreads();

        const float* pst = ps[buf];
        const int tbase = s * STG_T;
#pragma unroll 1
        for (int tl = 0; tl < STG_T; tl += 2) {
            {
                float hn = scan_step1(hs[0], w, pst[tl * HH + j]);
                hs[1][j] = hn;
                orow[(size_t)(tbase + tl) * HH] = hn;
                __syncthreads();
            }
            {
                float hn = scan_step1(hs[1], w, pst[(tl + 1) * HH + j]);
                hs[0][j] = hn;
                orow[(size_t)(tbase + tl + 1) * HH] = hn;
                __syncthreads();
            }
        }

        // refill stage s+2 into the buffer just consumed
        if (s + 2 < nst) {
            scan_prefetch(ps[buf], pre, (s + 2) * STG_T, j);
        }
        CP_COMMIT();
    }
}

// ---------------------------------------------------------------------------
extern "C" void kernel_launch(void* const* d_in, const int* in_sizes, int n_in,
                              void* d_out, int out_size)
{
    const float* x     = (const float*)d_in[0];
    const float* Wih0  = (const float*)d_in[1];
    const float* Whh0  = (const float*)d_in[2];
    const float* bih0  = (const float*)d_in[3];
    const float* bhh0  = (const float*)d_in[4];
    const float* Wih1  = (const float*)d_in[5];
    const float* Whh1  = (const float*)d_in[6];
    const float* bih1  = (const float*)d_in[7];
    const float* bhh1  = (const float*)d_in[8];
    float* out = (float*)d_out;

    // layer 0
    proj0_kernel<<<BB * TT / ROWS0, 128>>>(x, Wih0, bih0, bhh0);
    scan_kernel<<<BB, 128>>>(Whh0, nullptr);

    // layer 1
    proj1_kernel<<<PJ1_GRID, 128>>>(Wih1, bih1, bhh1);
    scan_kernel<<<BB, 128>>>(Whh1, out);
}